// round 17
// baseline (speedup 1.0000x reference)
#include <cuda_runtime.h>
#include <cuda_fp16.h>
#include <cstdint>

#define TOK  8192      // B*S
#define AH   512       // A = H*D
#define HIDW 1024
#define SEQ  2048
#define NH   8
#define HD   64
#define KW   9
#define QSC  0.18033688011112042f   // (1/8) * log2(e)

// ---------------- scratch (device globals; no allocation at launch) ----------------
__device__ __half g_hidh[TOK * HIDW];
__device__ __half g_wh  [5 * AH * AH];     // Wq, Wk, Wv, Wco, pw (fp16)
__device__ __half g_wckh[80 * AH];         // Wck padded to 80 rows (rows 72..79 = 0)
__device__ __half g_qh  [TOK * AH];
__device__ __half g_kh  [TOK * AH];
__device__ __half g_vh  [TOK * AH];
__device__ __half g_dwch[TOK * AH];
__device__ __half g_cah [TOK * AH];
__device__ float  g_col [TOK * AH];
__device__ float  g_ckl [TOK * NH * KW];

// ---------------- fast exp (softmax9) ------------------------------------------------
__device__ __forceinline__ float fexp(float x) {
    float y = fmaxf(x * 1.4426950408889634f, -126.0f);
    float z = y + 12582912.0f;
    int   ni = __float_as_int(z) - 0x4B400000;
    float f  = y - (z - 12582912.0f);
    float p  = 1.3333558146428443e-3f;
    p = fmaf(p, f, 9.6181291976353954e-3f);
    p = fmaf(p, f, 5.5504108664821580e-2f);
    p = fmaf(p, f, 2.4022650695910071e-1f);
    p = fmaf(p, f, 6.9314718055994531e-1f);
    p = fmaf(p, f, 1.0f);
    return p * __int_as_float(0x3F800000 + (ni << 23));
}

// exp2 on the MUFU pipe (issue-slot cheap; 2-ulp)
__device__ __forceinline__ float ex2f(float x) {
    float r;
    asm("ex2.approx.f32 %0, %1;" : "=f"(r) : "f"(x));
    return r;
}

// ---------------- mma / cp.async helpers ---------------------------------------------
__device__ __forceinline__ uint32_t cvta_s(const void* p) {
    return (uint32_t)__cvta_generic_to_shared(p);
}
__device__ __forceinline__ uint32_t f22h(float a, float b) {
    __half2 h = __floats2half2_rn(a, b);
    return *(uint32_t*)&h;
}
__device__ __forceinline__ void ldsm4(uint32_t& r0, uint32_t& r1, uint32_t& r2, uint32_t& r3, uint32_t a) {
    asm volatile("ldmatrix.sync.aligned.m8n8.x4.shared.b16 {%0,%1,%2,%3}, [%4];"
                 : "=r"(r0), "=r"(r1), "=r"(r2), "=r"(r3) : "r"(a));
}
__device__ __forceinline__ void ldsm4t(uint32_t& r0, uint32_t& r1, uint32_t& r2, uint32_t& r3, uint32_t a) {
    asm volatile("ldmatrix.sync.aligned.m8n8.x4.trans.shared.b16 {%0,%1,%2,%3}, [%4];"
                 : "=r"(r0), "=r"(r1), "=r"(r2), "=r"(r3) : "r"(a));
}
__device__ __forceinline__ void hmma(float* c, const uint32_t* a, const uint32_t* b) {
    asm volatile(
        "mma.sync.aligned.m16n8k16.row.col.f32.f16.f16.f32 "
        "{%0,%1,%2,%3}, {%4,%5,%6,%7}, {%8,%9}, {%0,%1,%2,%3};"
        : "+f"(c[0]), "+f"(c[1]), "+f"(c[2]), "+f"(c[3])
        : "r"(a[0]), "r"(a[1]), "r"(a[2]), "r"(a[3]), "r"(b[0]), "r"(b[1]));
}
__device__ __forceinline__ void cpa16(uint32_t dst, const void* src) {
    asm volatile("cp.async.cg.shared.global [%0], [%1], 16;" :: "r"(dst), "l"(src));
}
#define CPA_COMMIT asm volatile("cp.async.commit_group;")
#define CPA_WAIT0  asm volatile("cp.async.wait_group 0;")
#define CPA_WAIT1  asm volatile("cp.async.wait_group 1;")
#define CPA_WAIT2  asm volatile("cp.async.wait_group 2;")

// ---------------- one-shot fp32 -> fp16 conversion ----------------------------------
#define H8   (TOK * HIDW / 8)
#define W8   (AH * AH / 8)
#define WCK8 (80 * AH / 8)
#define CVT_BLKS ((H8 + 5 * W8 + WCK8) / 256)
__global__ void cvt_all(const float* __restrict__ hidden,
                        const float* __restrict__ Wq, const float* __restrict__ Wk,
                        const float* __restrict__ Wv, const float* __restrict__ Wco,
                        const float* __restrict__ pw, const float* __restrict__ Wck)
{
    int g = blockIdx.x * 256 + threadIdx.x;
    const float* src; __half* dst; int off;
    if (g < H8) {
        src = hidden; dst = g_hidh; off = g << 3;
    } else if (g < H8 + 5 * W8) {
        int u = g - H8; int which = u / W8; off = (u - which * W8) << 3;
        src = (which == 0) ? Wq : (which == 1) ? Wk : (which == 2) ? Wv
            : (which == 3) ? Wco : pw;
        dst = g_wh + which * (AH * AH);
    } else {
        int u = g - (H8 + 5 * W8); off = u << 3;
        if ((off >> 9) >= 72) { *(uint4*)&g_wckh[off] = make_uint4(0, 0, 0, 0); return; }
        src = Wck; dst = g_wckh;
    }
    float4 a = *(const float4*)(src + off);
    float4 b = *(const float4*)(src + off + 4);
    *(uint4*)&dst[off] = make_uint4(f22h(a.x, a.y), f22h(a.z, a.w), f22h(b.x, b.y), f22h(b.z, b.w));
}

// ==================== fp16 GEMM, cp.async 3-stage ring ===============================
#define GP      40
#define GABYTES (128 * GP * 2)     // 10240 per buffer
#define GEMM_SMEM (6 * GABYTES)    // 61440

__device__ __forceinline__ void gemm16_body(
    const __half* __restrict__ A, int lda,
    const __half* __restrict__ W,
    const float* __restrict__ bias,
    const __half* __restrict__ auxh, int ldaux,
    float* __restrict__ Cf, __half* __restrict__ Ch, int mode,
    __half* sm, int m0, int n0)
{
    const int t = threadIdx.x;
    const int w = t >> 5, l = t & 31;
    const int qq = l & 3, r = l >> 2;
    const int wm = (w & 1) << 6, wn = (w >> 1) << 5;

    const int srow = t & 127, skoff = (t >> 7) << 4;
    const __half* Ap = A + (size_t)(m0 + srow) * lda + skoff;
    const __half* Wp = W + (size_t)(n0 + srow) * AH + skoff;

    const uint32_t smb = cvta_s(sm);
    const uint32_t stA = smb + (srow * GP + skoff) * 2;
    const uint32_t stB = stA + 3 * GABYTES;

    auto stage = [&](int c, int bsx) {
        const __half* a = Ap + c * 32;
        const __half* b = Wp + c * 32;
        cpa16(stA + bsx * GABYTES,      a);
        cpa16(stA + bsx * GABYTES + 16, a + 8);
        cpa16(stB + bsx * GABYTES,      b);
        cpa16(stB + bsx * GABYTES + 16, b + 8);
        CPA_COMMIT;
    };

    float acc[4][4][4] = {};
    stage(0, 0); stage(1, 1);

    const uint32_t aoff = smb + ((wm + (l & 15)) * GP + ((l & 16) >> 1)) * 2;
    const uint32_t boff = smb + 3 * GABYTES +
                          ((wn + (l & 7) + ((l & 16) >> 1)) * GP + (l & 8)) * 2;

    int bs = 0, bs2 = 2;
    for (int c = 0; c < 16; c++) {
        if (c == 15) { CPA_WAIT0; } else { CPA_WAIT1; }
        __syncthreads();
        if (c + 2 < 16) stage(c + 2, bs2);
        const uint32_t ba = aoff + bs * GABYTES;
        const uint32_t bb = boff + bs * GABYTES;
        #pragma unroll
        for (int ks = 0; ks < 2; ks++) {
            const uint32_t kb = ks * 32;
            uint32_t bf[4][2];
            #pragma unroll
            for (int p = 0; p < 2; p++) {
                uint32_t r0, r1, r2, r3;
                ldsm4(r0, r1, r2, r3, bb + kb + p * (16 * GP * 2));
                bf[2*p][0] = r0; bf[2*p][1] = r1;
                bf[2*p+1][0] = r2; bf[2*p+1][1] = r3;
            }
            #pragma unroll
            for (int mt = 0; mt < 4; mt++) {
                uint32_t a0, a1, a2, a3;
                ldsm4(a0, a1, a2, a3, ba + kb + mt * (16 * GP * 2));
                uint32_t af[4] = {a0, a1, a2, a3};
                #pragma unroll
                for (int nt = 0; nt < 4; nt++)
                    hmma(acc[mt][nt], af, bf[nt]);
            }
        }
        bs  = (bs  == 2) ? 0 : bs + 1;
        bs2 = (bs2 == 2) ? 0 : bs2 + 1;
    }

    #pragma unroll
    for (int mt = 0; mt < 4; mt++) {
        const int m = m0 + wm + (mt << 4) + r;
        #pragma unroll
        for (int nt = 0; nt < 4; nt++) {
            const int n = n0 + wn + (nt << 3) + (qq << 1);
            float bb0 = bias[n], bb1 = bias[n + 1];
            float v0 = acc[mt][nt][0] + bb0;
            float v1 = acc[mt][nt][1] + bb1;
            float v2 = acc[mt][nt][2] + bb0;
            float v3 = acc[mt][nt][3] + bb1;
            if (mode == 1) { v0 *= QSC; v1 *= QSC; v2 *= QSC; v3 *= QSC; }
            if (mode == 4) {
                float2 x0 = __half22float2(*(const __half2*)&auxh[(size_t)m * ldaux + n]);
                float2 x1 = __half22float2(*(const __half2*)&auxh[(size_t)(m + 8) * ldaux + n]);
                v0 *= x0.x; v1 *= x0.y; v2 *= x1.x; v3 *= x1.y;
            }
            if (mode == 2) {
                *(float2*)&Cf[(size_t)m * AH + n]       = make_float2(v0, v1);
                *(float2*)&Cf[(size_t)(m + 8) * AH + n] = make_float2(v2, v3);
            } else {
                *(uint32_t*)&Ch[(size_t)m * AH + n]       = f22h(v0, v1);
                *(uint32_t*)&Ch[(size_t)(m + 8) * AH + n] = f22h(v2, v3);
            }
        }
    }
}

// fused {q,k,v} GEMM (blockIdx.z = op) — col moved to side stream
__global__ __launch_bounds__(256, 2) void gemm_qkv(
    const float* __restrict__ bq, const float* __restrict__ bk,
    const float* __restrict__ bv)
{
    extern __shared__ __half sm16[];
    const int op = blockIdx.z;
    const __half* W = g_wh + op * (AH * AH);
    const float* bias = (op == 0) ? bq : (op == 1) ? bk : bv;
    __half* Ch = (op == 0) ? g_qh : (op == 1) ? g_kh : g_vh;
    const int mode = (op == 0) ? 1 : 0;
    gemm16_body(g_hidh, HIDW, W, bias, nullptr, 0, nullptr, Ch, mode, sm16,
                blockIdx.y << 7, blockIdx.x << 7);
}

// col GEMM (side stream)
__global__ __launch_bounds__(256, 2) void gemm_col(const float* __restrict__ bco)
{
    extern __shared__ __half sm16[];
    gemm16_body(g_hidh + AH, HIDW, g_wh + 3 * (AH * AH), bco, nullptr, 0,
                g_col, nullptr, 2, sm16, blockIdx.y << 7, blockIdx.x << 7);
}

__global__ __launch_bounds__(256, 2) void gemm_ca_k(const float* __restrict__ sepb)
{
    extern __shared__ __half sm16[];
    gemm16_body(g_dwch, AH, g_wh + 4 * (AH * AH), sepb, g_hidh + AH, HIDW,
                nullptr, g_cah, 4, sm16, blockIdx.y << 7, blockIdx.x << 7);
}

// ==================== ckl tensor-core GEMM: [8192,72] ================================
#define CKB_BYTES (80 * GP * 2)                  // 6400
#define CKL_SMEM  (3 * (GABYTES + CKB_BYTES))    // 49920
__global__ __launch_bounds__(256, 2) void ckl16(const float* __restrict__ bck)
{
    extern __shared__ __half smc[];
    const int t = threadIdx.x, w = t >> 5, l = t & 31;
    const int qq = l & 3, r = l >> 2;
    const int m0 = blockIdx.x << 7;

    const int srow = t & 127, skoff = (t >> 7) << 4;
    const __half* Ap = g_cah + (size_t)(m0 + srow) * AH + skoff;
    const uint32_t smb = cvta_s(smc);
    const uint32_t stA = smb + (srow * GP + skoff) * 2;
    const int brow = t >> 1, bkoff = (t & 1) << 4;
    const __half* Bp = g_wckh + brow * AH + bkoff;
    const uint32_t stB = smb + 3 * GABYTES + (brow * GP + bkoff) * 2;

    auto stage = [&](int c, int bsx) {
        const __half* a = Ap + c * 32;
        cpa16(stA + bsx * GABYTES,      a);
        cpa16(stA + bsx * GABYTES + 16, a + 8);
        if (t < 160) {
            const __half* b = Bp + c * 32;
            cpa16(stB + bsx * CKB_BYTES,      b);
            cpa16(stB + bsx * CKB_BYTES + 16, b + 8);
        }
        CPA_COMMIT;
    };

    float acc[10][4] = {};
    stage(0, 0); stage(1, 1);

    const uint32_t aoff = smb + (((w << 4) + (l & 15)) * GP + ((l & 16) >> 1)) * 2;
    const uint32_t boff = smb + 3 * GABYTES +
                          (((l & 7) + ((l & 16) >> 1)) * GP + (l & 8)) * 2;

    int bs = 0, bs2 = 2;
    for (int c = 0; c < 16; c++) {
        if (c == 15) { CPA_WAIT0; } else { CPA_WAIT1; }
        __syncthreads();
        if (c + 2 < 16) stage(c + 2, bs2);
        #pragma unroll
        for (int ks = 0; ks < 2; ks++) {
            uint32_t a0, a1, a2, a3;
            ldsm4(a0, a1, a2, a3, aoff + bs * GABYTES + ks * 32);
            uint32_t af[4] = {a0, a1, a2, a3};
            #pragma unroll
            for (int p = 0; p < 5; p++) {
                uint32_t r0, r1, r2, r3;
                ldsm4(r0, r1, r2, r3, boff + bs * CKB_BYTES + ks * 32 + p * (16 * GP * 2));
                uint32_t bfa[2] = {r0, r1}, bfb[2] = {r2, r3};
                hmma(acc[2*p],     af, bfa);
                hmma(acc[2*p + 1], af, bfb);
            }
        }
        bs  = (bs  == 2) ? 0 : bs + 1;
        bs2 = (bs2 == 2) ? 0 : bs2 + 1;
    }

    const int m = m0 + (w << 4) + r;
    #pragma unroll
    for (int nt = 0; nt < 9; nt++) {
        int n = (nt << 3) + (qq << 1);
        if (n < 72) {
            float b0 = bck[n], b1 = bck[n + 1];
            *(float2*)&g_ckl[(size_t)m * 72 + n]       = make_float2(acc[nt][0] + b0, acc[nt][1] + b1);
            *(float2*)&g_ckl[(size_t)(m + 8) * 72 + n] = make_float2(acc[nt][2] + b0, acc[nt][3] + b1);
        }
    }
}

// ---------------- depthwise 9-tap conv, 2 channels/thread (fp16 in/out) -------------
__global__ void dwconv_k(const float* __restrict__ dw)
{
    int idx = blockIdx.x * 256 + threadIdx.x;
    int tok = idx >> 8, c2 = (idx & 255) << 1;
    int s = tok & (SEQ - 1);
    float ax = 0.f, ay = 0.f;
    #pragma unroll
    for (int k = 0; k < KW; k++) {
        int sp = s + k - 4;
        if ((unsigned)sp < (unsigned)SEQ) {
            float2 x = __half22float2(
                *(const __half2*)&g_hidh[(size_t)(tok + k - 4) * HIDW + AH + c2]);
            ax = fmaf(x.x, dw[c2 * KW + k], ax);
            ay = fmaf(x.y, dw[(c2 + 1) * KW + k], ay);
        }
    }
    *(uint32_t*)&g_dwch[(size_t)tok * AH + c2] = f22h(ax, ay);
}

// ---------------- softmax over K=9 groups --------------------------------------------
__global__ void softmax9_k()
{
    int id = blockIdx.x * 256 + threadIdx.x;
    float* p = g_ckl + (size_t)id * KW;
    float v[KW];
    float mx = -1e30f;
    #pragma unroll
    for (int k = 0; k < KW; k++) { v[k] = p[k]; mx = fmaxf(mx, v[k]); }
    float s = 0.f;
    #pragma unroll
    for (int k = 0; k < KW; k++) { v[k] = fexp(v[k] - mx); s += v[k]; }
    float inv = 1.f / s;
    #pragma unroll
    for (int k = 0; k < KW; k++) p[k] = v[k] * inv;
}

// ---------------- conv_out, 2 channels/thread ----------------------------------------
__global__ void convout_k(float* __restrict__ out)
{
    int idx = blockIdx.x * 256 + threadIdx.x;
    int tok = idx >> 8, c2 = (idx & 255) << 1;
    int s = tok & (SEQ - 1);
    int h = c2 >> 6;
    const float* cw = g_ckl + (size_t)tok * (NH * KW) + h * KW;
    float ax = 0.f, ay = 0.f;
    #pragma unroll
    for (int k = 0; k < KW; k++) {
        int sp = s + k - 4;
        if ((unsigned)sp < (unsigned)SEQ) {
            float2 x = *(const float2*)&g_col[(size_t)(tok + k - 4) * AH + c2];
            float wk = cw[k];
            ax = fmaf(x.x, wk, ax);
            ay = fmaf(x.y, wk, ay);
        }
    }
    *(float2*)&out[(size_t)tok * HIDW + AH + c2] = make_float2(ax, ay);
}

// ---------------- flash attention: register-resident P + MUFU exp2 -------------------
#define FPT   72
#define FKV   (64 * FPT)       // halves per K/V buffer
#define FKVB  (FKV * 2)        // 9216 bytes
#define FLASH_SMEM (6 * FKVB + 128 * FPT * 2)   // 73728
__global__ __launch_bounds__(256, 2) void flash16(float* __restrict__ out)
{
    extern __shared__ __half smf[];
    __half* Ks = smf;
    __half* Vs = smf + 3 * FKV;
    __half* Qs = smf + 6 * FKV;               // Q staging only

    const int bh = blockIdx.y, b = bh >> 3, h = bh & 7;
    const int q0 = blockIdx.x << 7;
    const int t = threadIdx.x, w = t >> 5, l = t & 31;
    const int qq = l & 3, r = l >> 2;
    const size_t base = (size_t)b * SEQ * AH + h * HD;

    const uint32_t sbK = cvta_s(Ks), sbV = cvta_s(Vs), sbQ = cvta_s(Qs);

    // Q stage (group 0)
    #pragma unroll
    for (int j = 0; j < 4; j++) {
        int fv = t + (j << 8);
        int row = fv >> 3, dblk = (fv & 7) << 3;
        cpa16(sbQ + (row * FPT + dblk) * 2,
              g_qh + base + (size_t)(q0 + row) * AH + dblk);
    }
    CPA_COMMIT;

    auto stageKV = [&](int i, int bsx) {
        #pragma unroll
        for (int j = 0; j < 2; j++) {
            int fv = t + (j << 8);
            int row = fv >> 3, dblk = (fv & 7) << 3;
            size_t g = base + (size_t)(i * 64 + row) * AH + dblk;
            cpa16(sbK + (bsx * FKV + row * FPT + dblk) * 2, g_kh + g);
            cpa16(sbV + (bsx * FKV + row * FPT + dblk) * 2, g_vh + g);
        }
        CPA_COMMIT;
    };
    stageKV(0, 0); stageKV(1, 1);

    CPA_WAIT2;           // Q done (KV0, KV1 still pending)
    __syncthreads();

    uint32_t qa[4][4];
    {
        const uint32_t qoff = sbQ + (((w << 4) + (l & 15)) * FPT + ((l & 16) >> 1)) * 2;
        #pragma unroll
        for (int tk = 0; tk < 4; tk++)
            ldsm4(qa[tk][0], qa[tk][1], qa[tk][2], qa[tk][3], qoff + (tk << 5));
    }

    float o[8][4] = {};
    float l0 = 0.f, l1 = 0.f;

    const uint32_t kfoff = sbK + ((((l & 7) + ((l & 16) >> 1)) * FPT + (l & 8)) * 2);
    const uint32_t vfoff = sbV + ((((l & 7) + (l & 8)) * FPT + ((l & 16) >> 1)) * 2);

    int bs = 0, bs2 = 2;
    for (int i = 0; i < 32; i++) {
        if (i == 31) { CPA_WAIT0; } else { CPA_WAIT1; }
        __syncthreads();
        if (i + 2 < 32) stageKV(i + 2, bs2);
        const uint32_t kb = bs * FKVB;

        // S = Q K^T (log2 units; scale folded into q in GEMM epilogue)
        float s[8][4] = {};
        #pragma unroll
        for (int tk = 0; tk < 4; tk++) {
            #pragma unroll
            for (int p = 0; p < 4; p++) {
                uint32_t k0, k1, k2, k3;
                ldsm4(k0, k1, k2, k3, kfoff + kb + (p * 16 * FPT + tk * 16) * 2);
                uint32_t bfa[2] = {k0, k1}, bfb[2] = {k2, k3};
                hmma(s[2*p],     qa[tk], bfa);
                hmma(s[2*p + 1], qa[tk], bfb);
            }
        }

        // exp2 (MUFU) and direct C-frag -> A-frag conversion (register-resident P)
        uint32_t pf[4][4];
        float rs0 = 0.f, rs1 = 0.f;
        #pragma unroll
        for (int nt = 0; nt < 8; nt++) {
            float p0 = ex2f(s[nt][0]);
            float p1 = ex2f(s[nt][1]);
            float p2 = ex2f(s[nt][2]);
            float p3 = ex2f(s[nt][3]);
            rs0 += p0 + p1; rs1 += p2 + p3;
            pf[nt >> 1][((nt & 1) << 1) + 0] = f22h(p0, p1);   // row r
            pf[nt >> 1][((nt & 1) << 1) + 1] = f22h(p2, p3);   // row r+8
        }
        rs0 += __shfl_xor_sync(0xffffffffu, rs0, 1);
        rs0 += __shfl_xor_sync(0xffffffffu, rs0, 2);
        rs1 += __shfl_xor_sync(0xffffffffu, rs1, 1);
        rs1 += __shfl_xor_sync(0xffffffffu, rs1, 2);
        l0 += rs0; l1 += rs1;

        // O += P V   (P in registers; V via ldmatrix.trans)
        #pragma unroll
        for (int tk = 0; tk < 4; tk++) {
            #pragma unroll
            for (int p = 0; p < 4; p++) {
                uint32_t v0, v1, v2, v3;
                ldsm4t(v0, v1, v2, v3, vfoff + kb + (tk * 16 * FPT + p * 16) * 2);
                uint32_t bfa[2] = {v0, v1}, bfb[2] = {v2, v3};
                hmma(o[2*p],     pf[tk], bfa);
                hmma(o[2*p + 1], pf[tk], bfb);
            }
        }
        bs  = (bs  == 2) ? 0 : bs + 1;
        bs2 = (bs2 == 2) ? 0 : bs2 + 1;
    }

    float inv0 = 1.f / l0, inv1 = 1.f / l1;
    int row0 = b * SEQ + q0 + (w << 4) + r;
    #pragma unroll
    for (int nt = 0; nt < 8; nt++) {
        int col = h * HD + (nt << 3) + (qq << 1);
        *(float2*)&out[(size_t)row0 * HIDW + col]       = make_float2(o[nt][0] * inv0, o[nt][1] * inv0);
        *(float2*)&out[(size_t)(row0 + 8) * HIDW + col] = make_float2(o[nt][2] * inv1, o[nt][3] * inv1);
    }
}

// ---------------- launch ---------------------------------------------------------------
extern "C" void kernel_launch(void* const* d_in, const int* in_sizes, int n_in,
                              void* d_out, int out_size)
{
    const float* hidden = (const float*)d_in[0];
    const float* Wq  = (const float*)d_in[1];
    const float* bq  = (const float*)d_in[2];
    const float* Wk  = (const float*)d_in[3];
    const float* bk  = (const float*)d_in[4];
    const float* Wv  = (const float*)d_in[5];
    const float* bv  = (const float*)d_in[6];
    const float* dw  = (const float*)d_in[7];
    const float* pw  = (const float*)d_in[8];
    const float* sepb= (const float*)d_in[9];
    const float* Wck = (const float*)d_in[10];
    const float* bck = (const float*)d_in[11];
    const float* Wco = (const float*)d_in[12];
    const float* bco = (const float*)d_in[13];
    float* out = (float*)d_out;

    static cudaStream_t s2 = nullptr;
    static cudaEvent_t evF = nullptr, evJ = nullptr;
    if (!s2) {
        cudaStreamCreateWithFlags(&s2, cudaStreamNonBlocking);
        cudaEventCreateWithFlags(&evF, cudaEventDisableTiming);
        cudaEventCreateWithFlags(&evJ, cudaEventDisableTiming);
        cudaFuncSetAttribute(gemm_qkv,  cudaFuncAttributeMaxDynamicSharedMemorySize, GEMM_SMEM);
        cudaFuncSetAttribute(gemm_col,  cudaFuncAttributeMaxDynamicSharedMemorySize, GEMM_SMEM);
        cudaFuncSetAttribute(gemm_ca_k, cudaFuncAttributeMaxDynamicSharedMemorySize, GEMM_SMEM);
        cudaFuncSetAttribute(ckl16,     cudaFuncAttributeMaxDynamicSharedMemorySize, CKL_SMEM);
        cudaFuncSetAttribute(flash16,   cudaFuncAttributeMaxDynamicSharedMemorySize, FLASH_SMEM);
    }

    // 1. conversions on main stream
    cvt_all<<<CVT_BLKS, 256>>>(hidden, Wq, Wk, Wv, Wco, pw, Wck);

    // fork: side stream runs the whole conv-attention branch INCLUDING col + convout
    cudaEventRecord(evF, 0);
    cudaStreamWaitEvent(s2, evF, 0);

    dwconv_k<<<TOK, 256, 0, s2>>>(dw);
    gemm_ca_k<<<dim3(AH / 128, TOK / 128), 256, GEMM_SMEM, s2>>>(sepb);
    ckl16<<<TOK / 128, 256, CKL_SMEM, s2>>>(bck);
    softmax9_k<<<TOK * NH / 256, 256, 0, s2>>>();
    gemm_col<<<dim3(AH / 128, TOK / 128), 256, GEMM_SMEM, s2>>>(bco);
    convout_k<<<TOK, 256, 0, s2>>>(out);
    cudaEventRecord(evJ, s2);

    // main stream: exactly flash's prerequisites, then flash
    gemm_qkv<<<dim3(AH / 128, TOK / 128, 3), 256, GEMM_SMEM>>>(bq, bk, bv);
    flash16<<<dim3(SEQ / 128, 32), 256, FLASH_SMEM>>>(out);

    // join side stream
    cudaStreamWaitEvent(0, evJ, 0);
}